// round 16
// baseline (speedup 1.0000x reference)
#include <cuda_runtime.h>

// Locally-connected 2D: out[oy,ox] = sum_{ky,kx} x[oy+ky, ox+kx] * W[oy,ox,ky,kx]
// x: [450,450] f32, W: [436,436,15,15] f32 (171 MB streamed once), out: [436,436].
//
// 4-pixel rolling software pipeline per warp (Little's-law optimization,
// extending the 2-pixel version that took 37.4 -> 33.2 us). Pixels are
// pix + i*QUART, QUART = NPIX/4 = 109*436: same column, +109*i rows, so all
// x addressing is pixel-0 pointers + compile-time offsets. Two 7-float W
// register buffers are renamed through the pipeline so ~1800B stay in flight
// during nearly all compute; only the last pixel's compute is dry.

#define IN_H 450
#define IN_W 450
#define KH 15
#define KW 15
#define OH 436
#define OW 436
#define KSIZE 225
#define NPIX (OH * OW)        // 190096
#define QUART (NPIX / 4)      // 47524 = 109 * 436
#define XSTEP (109 * IN_W)    // x float-offset between successive pixels
#define PFD 96                // prefetch distance in pixels

#define LOADW(buf, ptr)                     \
    buf##0 = __ldcs(ptr);                   \
    buf##1 = __ldcs(ptr + 32);              \
    buf##2 = __ldcs(ptr + 64);              \
    buf##3 = __ldcs(ptr + 96);              \
    buf##4 = __ldcs(ptr + 128);             \
    buf##5 = __ldcs(ptr + 160);             \
    buf##6 = __ldcs(ptr + 192);

__global__ __launch_bounds__(256)
void lc2d_kernel(const float* __restrict__ x,
                 const float* __restrict__ W,
                 float* __restrict__ out)
{
    const int lane = threadIdx.x & 31;
    const int pix  = (blockIdx.x * blockDim.x + threadIdx.x) >> 5;
    if (pix >= QUART) return;

    const int oy = pix / OW;
    const int ox = pix - oy * OW;

    const float* wp0 = W + (size_t)pix * KSIZE + lane;
    const float* wp1 = wp0 + (size_t)QUART * KSIZE;
    const float* wp2 = wp1 + (size_t)QUART * KSIZE;
    const float* wp3 = wp2 + (size_t)QUART * KSIZE;

    // L2 prefetch for all 4 streams, PFD pixels ahead.
    if (lane < 8 && pix + PFD < QUART) {
        const char* pf = (const char*)(W + (size_t)(pix + PFD) * KSIZE) + lane * 128;
        const size_t qb = (size_t)QUART * KSIZE * 4;
        asm volatile("prefetch.global.L2 [%0];" :: "l"(pf));
        asm volatile("prefetch.global.L2 [%0];" :: "l"(pf + qb));
        asm volatile("prefetch.global.L2 [%0];" :: "l"(pf + 2 * qb));
        asm volatile("prefetch.global.L2 [%0];" :: "l"(pf + 3 * qb));
    }

    // W register double-buffer.
    float a0, a1, a2, a3, a4, a5, a6;
    float b0, b1, b2, b3, b4, b5, b6;
    LOADW(a, wp0)                      // P0 weights
    LOADW(b, wp1)                      // P1 weights (stay in flight thru P0)

    // Per-lane x pointers for pixel 0; pixels i use +i*XSTEP.
    const float* xbase = x + oy * IN_W + ox;
    const float* xp0; const float* xp1; const float* xp2; const float* xp3;
    const float* xp4; const float* xp5; const float* xp6;
    {
        int k, ky;
        k = lane;       ky = k / KW; xp0 = xbase + ky * IN_W + (k - ky * KW);
        k = lane + 32;  ky = k / KW; xp1 = xbase + ky * IN_W + (k - ky * KW);
        k = lane + 64;  ky = k / KW; xp2 = xbase + ky * IN_W + (k - ky * KW);
        k = lane + 96;  ky = k / KW; xp3 = xbase + ky * IN_W + (k - ky * KW);
        k = lane + 128; ky = k / KW; xp4 = xbase + ky * IN_W + (k - ky * KW);
        k = lane + 160; ky = k / KW; xp5 = xbase + ky * IN_W + (k - ky * KW);
        k = lane + 192; ky = k / KW; xp6 = xbase + ky * IN_W + (k - ky * KW);
    }

    // Compute one pixel from a W buffer; tail k=224 on lane 0; reduce; store.
#define DO_PIXEL(buf, XO, wp, opix)                                          \
    {                                                                        \
        const float v0 = __ldg(xp0 + (XO));                                  \
        const float v1 = __ldg(xp1 + (XO));                                  \
        const float v2 = __ldg(xp2 + (XO));                                  \
        const float v3 = __ldg(xp3 + (XO));                                  \
        const float v4 = __ldg(xp4 + (XO));                                  \
        const float v5 = __ldg(xp5 + (XO));                                  \
        const float v6 = __ldg(xp6 + (XO));                                  \
        float s0 = buf##0 * v0;                                              \
        float s1 = buf##1 * v1;                                              \
        s0 = fmaf(buf##2, v2, s0);                                           \
        s1 = fmaf(buf##3, v3, s1);                                           \
        s0 = fmaf(buf##4, v4, s0);                                           \
        s1 = fmaf(buf##5, v5, s1);                                           \
        s0 = fmaf(buf##6, v6, s0);                                           \
        if (lane == 0)                                                       \
            s1 = fmaf(__ldcs(wp + 224),                                      \
                      __ldg(xbase + (XO) + 14 * IN_W + 14), s1);             \
        float sum = s0 + s1;                                                 \
        _Pragma("unroll")                                                    \
        for (int off = 16; off > 0; off >>= 1)                               \
            sum += __shfl_down_sync(0xffffffffu, sum, off);                  \
        if (lane == 0)                                                       \
            out[opix] = sum;                                                 \
    }

    DO_PIXEL(a, 0, wp0, pix)                       // P1 loads in flight
    LOADW(a, wp2)                                  // refill: P2 in flight
    DO_PIXEL(b, XSTEP, wp1, pix + QUART)
    LOADW(b, wp3)                                  // refill: P3 in flight
    DO_PIXEL(a, 2 * XSTEP, wp2, pix + 2 * QUART)
    DO_PIXEL(b, 3 * XSTEP, wp3, pix + 3 * QUART)   // dry stretch (only one)

#undef DO_PIXEL
}

extern "C" void kernel_launch(void* const* d_in, const int* in_sizes, int n_in,
                              void* d_out, int out_size)
{
    const float* x = (const float*)d_in[0];
    const float* W = (const float*)d_in[1];
    float* out = (float*)d_out;

    const int threads = 256;                // 8 warps = 8 pixel-quads per block
    const int blocks = (QUART + 7) / 8;     // 5941
    lc2d_kernel<<<blocks, threads>>>(x, W, out);
}

// round 17
// speedup vs baseline: 1.1309x; 1.1309x over previous
#include <cuda_runtime.h>

// Locally-connected 2D: out[oy,ox] = sum_{ky,kx} x[oy+ky, ox+kx] * W[oy,ox,ky,kx]
// x: [450,450] f32, W: [436,436,15,15] f32 (171 MB streamed once), out: [436,436].
//
// 3-stream all-up-front pipeline (Little's law). Each warp owns pixels
// pix + i*T, T = 146*436 (same column, +146*i rows -> x addressing is
// pixel-0 pointers + compile-time offsets). ALL 21 W loads issue in one
// contiguous batch before any consumer (the pattern ptxas preserved in the
// 33.2us 2-stream version; the interleaved-refill variant got its loads
// sunk at regs=32). In-flight W bytes decay 2700->1800->900 across the
// three computes instead of 1800->900->0 over two. Third stream guarded
// (covers the tail; guard is warp-uniform). launch_bounds(256,4) lifts the
// reg cap so the load batch can stay live.

#define IN_H 450
#define IN_W 450
#define KH 15
#define KW 15
#define OH 436
#define OW 436
#define KSIZE 225
#define NPIX (OH * OW)        // 190096
#define TSTRIDE (146 * OW)    // 63656 pixels between streams
#define XS (146 * IN_W)       // x float-offset between streams
#define NWARP TSTRIDE         // warps launched (covers streams 0/1 fully)
#define PFD 96                // prefetch distance in pixels

__global__ __launch_bounds__(256, 4)
void lc2d_kernel(const float* __restrict__ x,
                 const float* __restrict__ W,
                 float* __restrict__ out)
{
    const int lane = threadIdx.x & 31;
    const int pix  = (blockIdx.x * blockDim.x + threadIdx.x) >> 5;
    if (pix >= NWARP) return;

    const bool has2 = (pix + 2 * TSTRIDE) < NPIX;   // tail guard (warp-uniform)

    const int oy = pix / OW;
    const int ox = pix - oy * OW;

    const float* wp0 = W + (size_t)pix * KSIZE + lane;
    const float* wp1 = wp0 + (size_t)TSTRIDE * KSIZE;
    const float* wp2 = wp1 + (size_t)TSTRIDE * KSIZE;

    // L2 prefetch for all streams, PFD pixels ahead.
    if (lane < 8 && pix + PFD < NWARP) {
        const char* pf = (const char*)(W + (size_t)(pix + PFD) * KSIZE) + lane * 128;
        const size_t tb = (size_t)TSTRIDE * KSIZE * 4;
        asm volatile("prefetch.global.L2 [%0];" :: "l"(pf));
        asm volatile("prefetch.global.L2 [%0];" :: "l"(pf + tb));
        if (has2)
            asm volatile("prefetch.global.L2 [%0];" :: "l"(pf + 2 * tb));
    }

    // ---- ALL W loads up front: up to 2700B in flight per warp ----
    const float a0 = __ldcs(wp0);
    const float a1 = __ldcs(wp0 + 32);
    const float a2 = __ldcs(wp0 + 64);
    const float a3 = __ldcs(wp0 + 96);
    const float a4 = __ldcs(wp0 + 128);
    const float a5 = __ldcs(wp0 + 160);
    const float a6 = __ldcs(wp0 + 192);
    const float b0 = __ldcs(wp1);
    const float b1 = __ldcs(wp1 + 32);
    const float b2 = __ldcs(wp1 + 64);
    const float b3 = __ldcs(wp1 + 96);
    const float b4 = __ldcs(wp1 + 128);
    const float b5 = __ldcs(wp1 + 160);
    const float b6 = __ldcs(wp1 + 192);
    float c0 = 0.f, c1 = 0.f, c2 = 0.f, c3 = 0.f, c4 = 0.f, c5 = 0.f, c6 = 0.f;
    if (has2) {
        c0 = __ldcs(wp2);
        c1 = __ldcs(wp2 + 32);
        c2 = __ldcs(wp2 + 64);
        c3 = __ldcs(wp2 + 96);
        c4 = __ldcs(wp2 + 128);
        c5 = __ldcs(wp2 + 160);
        c6 = __ldcs(wp2 + 192);
    }

    // Per-lane x pointers for pixel 0 (ALU overlaps the W miss latency);
    // streams 1/2 use +XS, +2*XS compile-time offsets.
    const float* xbase = x + oy * IN_W + ox;
    const float* xp0; const float* xp1; const float* xp2; const float* xp3;
    const float* xp4; const float* xp5; const float* xp6;
    {
        int k, ky;
        k = lane;       ky = k / KW; xp0 = xbase + ky * IN_W + (k - ky * KW);
        k = lane + 32;  ky = k / KW; xp1 = xbase + ky * IN_W + (k - ky * KW);
        k = lane + 64;  ky = k / KW; xp2 = xbase + ky * IN_W + (k - ky * KW);
        k = lane + 96;  ky = k / KW; xp3 = xbase + ky * IN_W + (k - ky * KW);
        k = lane + 128; ky = k / KW; xp4 = xbase + ky * IN_W + (k - ky * KW);
        k = lane + 160; ky = k / KW; xp5 = xbase + ky * IN_W + (k - ky * KW);
        k = lane + 192; ky = k / KW; xp6 = xbase + ky * IN_W + (k - ky * KW);
    }

#define DO_PIXEL(W0, W1, W2, W3, W4, W5, W6, XO, wp, opix)                   \
    {                                                                        \
        const float v0 = __ldg(xp0 + (XO));                                  \
        const float v1 = __ldg(xp1 + (XO));                                  \
        const float v2 = __ldg(xp2 + (XO));                                  \
        const float v3 = __ldg(xp3 + (XO));                                  \
        const float v4 = __ldg(xp4 + (XO));                                  \
        const float v5 = __ldg(xp5 + (XO));                                  \
        const float v6 = __ldg(xp6 + (XO));                                  \
        float s0 = W0 * v0;                                                  \
        float s1 = W1 * v1;                                                  \
        s0 = fmaf(W2, v2, s0);                                               \
        s1 = fmaf(W3, v3, s1);                                               \
        s0 = fmaf(W4, v4, s0);                                               \
        s1 = fmaf(W5, v5, s1);                                               \
        s0 = fmaf(W6, v6, s0);                                               \
        if (lane == 0)                                                       \
            s1 = fmaf(__ldcs(wp + 224),                                      \
                      __ldg(xbase + (XO) + 14 * IN_W + 14), s1);             \
        float sum = s0 + s1;                                                 \
        _Pragma("unroll")                                                    \
        for (int off = 16; off > 0; off >>= 1)                               \
            sum += __shfl_down_sync(0xffffffffu, sum, off);                  \
        if (lane == 0)                                                       \
            out[opix] = sum;                                                 \
    }

    DO_PIXEL(a0, a1, a2, a3, a4, a5, a6, 0,       wp0, pix)
    DO_PIXEL(b0, b1, b2, b3, b4, b5, b6, XS,      wp1, pix + TSTRIDE)
    if (has2)
        DO_PIXEL(c0, c1, c2, c3, c4, c5, c6, 2 * XS, wp2, pix + 2 * TSTRIDE)

#undef DO_PIXEL
}

extern "C" void kernel_launch(void* const* d_in, const int* in_sizes, int n_in,
                              void* d_out, int out_size)
{
    const float* x = (const float*)d_in[0];
    const float* W = (const float*)d_in[1];
    float* out = (float*)d_out;

    const int threads = 256;                  // 8 warps per block
    const int blocks = (NWARP + 7) / 8;       // 7957
    lc2d_kernel<<<blocks, threads>>>(x, W, out);
}